// round 10
// baseline (speedup 1.0000x reference)
#include <cuda_runtime.h>
#include <math.h>
#include <cstdint>

// Problem dims (fixed)
#define BDIM 2
#define TDIM 2048
#define CDIM 1024
#define NH   16
#define HD   64
#define MROWS (BDIM*TDIM)   // 4096

// ---------------- device scratch (no allocations allowed) ----------------
__device__ float g_q[(size_t)MROWS*CDIM];   // q after rope (natural layout)
__device__ float g_k[(size_t)MROWS*HD];     // k pre-rope (natural, gemm out)
__device__ float g_k2[(size_t)MROWS*HD];    // k post-rope, paired-transposed tiles
__device__ float g_v[(size_t)MROWS*HD];     // v paired tiles (gemm writes directly)
__device__ float g_att[(size_t)MROWS*CDIM]; // attn out: tf32-rounded, PAIRED-K in 8-groups
__device__ float g_xr[(size_t)MROWS*CDIM];  // x : tf32-rounded, PAIRED-K in 8-groups
__device__ float g_wqr[(size_t)CDIM*CDIM];  // Wq: tf32-rounded, row-PAIRED (K2-style)
__device__ float g_wor[(size_t)CDIM*CDIM];  // Wo: tf32-rounded, row-PAIRED

// Paired-K (A-side) layout: within each 8-float k-group [x0..x7] store
//   [x0,x4,x1,x5,x2,x6,x3,x7]   (pos(q) = 2*(q&3) + (q>>2))
// Row-paired (B-side) layout: paired-row pr=(k>>3)*4+(k&3) holds float2
//   ( B[k][n], B[k+4][n] )  for k with (k>>2)&1==0.

// ======================= helpers =========================================
__device__ __forceinline__ float to_tf32(float x) {
    float r; asm("cvt.rna.tf32.f32 %0, %1;" : "=f"(r) : "f"(x)); return r;
}
__device__ __forceinline__ void mma_tf32(float* c,
    uint32_t a0, uint32_t a1, uint32_t a2, uint32_t a3,
    uint32_t b0, uint32_t b1)
{
    asm volatile(
        "mma.sync.aligned.m16n8k8.row.col.f32.tf32.tf32.f32 "
        "{%0,%1,%2,%3}, {%4,%5,%6,%7}, {%8,%9}, {%0,%1,%2,%3};"
        : "+f"(c[0]), "+f"(c[1]), "+f"(c[2]), "+f"(c[3])
        : "r"(a0), "r"(a1), "r"(a2), "r"(a3), "r"(b0), "r"(b1));
}
__device__ __forceinline__ uint32_t smem_u32(const void* p) {
    uint32_t a;
    asm("{ .reg .u64 t; cvta.to.shared.u64 t, %1; cvt.u32.u64 %0, t; }"
        : "=r"(a) : "l"(p));
    return a;
}
#define CP_ASYNC16(dst_u32, src_ptr) \
    asm volatile("cp.async.cg.shared.global [%0], [%1], 16;" \
        :: "r"(dst_u32), "l"(src_ptr) : "memory")
#define CP_COMMIT() asm volatile("cp.async.commit_group;" ::: "memory")
#define CP_WAIT0()  asm volatile("cp.async.wait_group 0;"  ::: "memory")
#define CP_WAIT1()  asm volatile("cp.async.wait_group 1;"  ::: "memory")

// =========================================================================
// pairK_round: A-side prep. out = paired-K permutation of tf32(in).
// One thread per 8-float group.
// =========================================================================
__global__ void pairK_round_kernel(const float4* __restrict__ in,
                                   float4* __restrict__ out, int ngroups)
{
    int i = blockIdx.x * blockDim.x + threadIdx.x;
    if (i >= ngroups) return;
    float4 a = in[i*2], b = in[i*2+1];
    a.x=to_tf32(a.x); a.y=to_tf32(a.y); a.z=to_tf32(a.z); a.w=to_tf32(a.w);
    b.x=to_tf32(b.x); b.y=to_tf32(b.y); b.z=to_tf32(b.z); b.w=to_tf32(b.w);
    out[i*2]   = make_float4(a.x, b.x, a.y, b.y);
    out[i*2+1] = make_float4(a.z, b.z, a.w, b.w);
}

// =========================================================================
// pairB_round: B-side prep for W[K=1024][N=1024].
// Thread owns (j,q,n4): reads rows 8j+q and 8j+q+4 (float4 of cols),
// writes interleaved float2 pairs at paired-row 4j+q.
// =========================================================================
__global__ void pairB_round_kernel(const float* __restrict__ in,
                                   float4* __restrict__ out)
{
    int i = blockIdx.x * blockDim.x + threadIdx.x;   // < 128*4*256
    if (i >= 128*4*256) return;
    int n4 = i & 255;
    int q  = (i >> 8) & 3;
    int j  = i >> 10;
    const float* r0 = in + (size_t)(8*j + q)     * CDIM + n4*4;
    const float* r1 = in + (size_t)(8*j + q + 4) * CDIM + n4*4;
    float a0=to_tf32(r0[0]), a1=to_tf32(r0[1]), a2=to_tf32(r0[2]), a3=to_tf32(r0[3]);
    float b0=to_tf32(r1[0]), b1=to_tf32(r1[1]), b2=to_tf32(r1[2]), b3=to_tf32(r1[3]);
    size_t o4 = (size_t)(4*j + q) * 512 + n4*2;   // float4 index
    out[o4]   = make_float4(a0, b0, a1, b1);
    out[o4+1] = make_float4(a2, b2, a3, b3);
}

// =========================================================================
// 3-stage cp.async pipelined tf32 GEMM, paired operands:
//   C[M,N] = A2[M,K](paired-K) @ B2[K,N](row-paired) + bias[N]
// BM=256, BN=128, BK=16, 256 threads = 8 warps (4m x 2n), warp 64x64.
// grid = (N/128, M/256) = (8,16) = 128 CTAs (single wave on 148 SMs).
// =========================================================================
#define G2_AS   20                   // A smem row stride (floats)
#define G2_BP2S 132                  // B smem paired-row stride (float2)
#define G2_ASTF (256*G2_AS)          // 5120 floats
#define G2_BSTF (8*G2_BP2S*2)        // 2112 floats
#define G2_STF  (G2_ASTF+G2_BSTF)    // 7232 floats per stage
#define G2_SMEM (3*G2_STF*4)         // 86784 bytes

__global__ void __launch_bounds__(256)
tc_gemm_pipe2_kernel(const float* __restrict__ A2, const float* __restrict__ B2,
                     const float* __restrict__ bias, float* __restrict__ C,
                     int M, int N, int K)
{
    extern __shared__ float sm[];
    const uint32_t sbase = smem_u32(sm);

    const int tid   = threadIdx.x;
    const int lane  = tid & 31;
    const int w     = tid >> 5;
    const int warpM = w >> 1;               // 0..3
    const int warpN = w & 1;                // 0..1
    const int g     = lane >> 2;
    const int qd    = lane & 3;
    const int rowBase = blockIdx.y * 256;
    const int colBase = blockIdx.x * 128;

    // 6 cp.async 16B chunks/thread/stage: A=1024 chunks, B=512 chunks
    const char* gsrc[6]; uint32_t soff[6]; size_t jstr[6];
#pragma unroll
    for (int i = 0; i < 6; i++) {
        int idx = tid + i * 256;
        if (idx < 1024) {                   // A: row r, 4 chunks of 16B
            int r = idx >> 2, c4 = (idx & 3) * 16;
            gsrc[i] = (const char*)(A2 + (size_t)(rowBase + r) * K) + c4;
            soff[i] = (uint32_t)(r * G2_AS * 4 + c4);
            jstr[i] = 16 * 4;               // BK floats per j
        } else {                            // B: paired rows 8j..8j+7
            int e = idx - 1024;
            int prl = e >> 6, ch = (e & 63) * 16;
            gsrc[i] = (const char*)B2 + (size_t)prl * (CDIM*8) + colBase*8 + ch;
            soff[i] = (uint32_t)(G2_ASTF*4 + prl * (G2_BP2S*8) + ch);
            jstr[i] = (size_t)8 * CDIM * 8; // 8 paired rows per j
        }
    }
    auto issue = [&](int j, int s) {
        const uint32_t sb = sbase + (uint32_t)s * (G2_STF * 4);
#pragma unroll
        for (int i = 0; i < 6; i++)
            CP_ASYNC16(sb + soff[i], gsrc[i] + (size_t)j * jstr[i]);
        CP_COMMIT();
    };

    const int NI = K / 16;   // 64

    float acc[4][8][4];
#pragma unroll
    for (int mt = 0; mt < 4; mt++)
#pragma unroll
        for (int nt = 0; nt < 8; nt++)
#pragma unroll
            for (int i = 0; i < 4; i++) acc[mt][nt][i] = 0.0f;

    issue(0, 0);
    issue(1, 1);

    int s = 0;
    for (int j = 0; j < NI; j++) {
        CP_WAIT1();
        __syncthreads();

        if (j + 2 < NI) {
            int s2 = s + 2; if (s2 >= 3) s2 -= 3;
            issue(j + 2, s2);
        } else {
            CP_COMMIT();   // empty group keeps wait_group accounting aligned
        }

        const float*  Ab  = sm + s * G2_STF;
        const float2* Bb2 = (const float2*)(Ab + G2_ASTF);
#pragma unroll
        for (int kk = 0; kk < 16; kk += 8) {
            float2 afl[4], afh[4];
#pragma unroll
            for (int mt = 0; mt < 4; mt++) {
                const int m0 = warpM * 64 + mt * 16;
                afl[mt] = *(const float2*)&Ab[(m0 + g    ) * G2_AS + kk + 2*qd];
                afh[mt] = *(const float2*)&Ab[(m0 + g + 8) * G2_AS + kk + 2*qd];
            }
            float2 bf[8];
#pragma unroll
            for (int nt = 0; nt < 8; nt++) {
                const int n0 = warpN * 64 + nt * 8;
                bf[nt] = Bb2[((kk >> 1) + qd) * G2_BP2S + n0 + g];
            }
#pragma unroll
            for (int mt = 0; mt < 4; mt++)
#pragma unroll
                for (int nt = 0; nt < 8; nt++)
                    mma_tf32(acc[mt][nt],
                             __float_as_uint(afl[mt].x), __float_as_uint(afh[mt].x),
                             __float_as_uint(afl[mt].y), __float_as_uint(afh[mt].y),
                             __float_as_uint(bf[nt].x),  __float_as_uint(bf[nt].y));
        }
        if (++s == 3) s = 0;
    }

#pragma unroll
    for (int mt = 0; mt < 4; mt++) {
        const int row0 = rowBase + warpM * 64 + mt * 16 + g;
#pragma unroll
        for (int nt = 0; nt < 8; nt++) {
            const int c = colBase + warpN * 64 + nt * 8 + qd * 2;
            const float b0 = bias[c], b1 = bias[c + 1];
            float2 v0 = make_float2(acc[mt][nt][0] + b0, acc[mt][nt][1] + b1);
            float2 v1 = make_float2(acc[mt][nt][2] + b0, acc[mt][nt][3] + b1);
            *(float2*)&C[(size_t)row0 * N + c] = v0;
            *(float2*)&C[(size_t)(row0 + 8) * N + c] = v1;
        }
    }
}

// =========================================================================
// K and V projections fused: z=0 -> K natural, z=1 -> V paired tiles.
// =========================================================================
__global__ void __launch_bounds__(256)
tc_gemm_kv_kernel(const float* __restrict__ A,
                  const float* __restrict__ B0, const float* __restrict__ bias0,
                  float* __restrict__ C0,
                  const float* __restrict__ B1, const float* __restrict__ bias1,
                  float* __restrict__ C1,
                  int M, int N, int K)
{
    constexpr int BN  = 64;
    constexpr int BM  = 128;
    constexpr int BK  = 16;
    constexpr int AS  = BK + 4;
    constexpr int BNS = BN + 8;
    constexpr int A_FLOATS = BM * AS;
    constexpr int B_FLOATS = BK * BNS;
    constexpr int A_F4 = BM * BK / (4 * 256);
    constexpr int B_F4 = BK * BN / (4 * 256);
    constexpr int NT   = BN / 32;
    constexpr int WN   = BN / 4;

    const float* B    = blockIdx.z ? B1 : B0;
    const float* bias = blockIdx.z ? bias1 : bias0;
    float*       C    = blockIdx.z ? C1 : C0;

    extern __shared__ float sm[];
    float* As = sm;
    float* Bs = sm + 2 * A_FLOATS;

    const int tid   = threadIdx.x;
    const int lane  = tid & 31;
    const int w     = tid >> 5;
    const int warpM = w & 1;
    const int warpN = w >> 1;
    const int g     = lane >> 2;
    const int qd    = lane & 3;
    const int rowBase = blockIdx.y * BM;

    int ar[A_F4]; int akq[A_F4];
#pragma unroll
    for (int t = 0; t < A_F4; t++) {
        int idx = tid + t * 256;
        ar[t] = idx >> 2; akq[t] = (idx & 3) * 4;
    }
    int br[B_F4]; int bc4[B_F4];
#pragma unroll
    for (int t = 0; t < B_F4; t++) {
        int idx = tid + t * 256;
        br[t] = idx / (BN / 4); bc4[t] = (idx % (BN / 4)) * 4;
    }

    const int NI = K / BK;

    float acc[4][NT][4];
#pragma unroll
    for (int mt = 0; mt < 4; mt++)
#pragma unroll
        for (int nt = 0; nt < NT; nt++)
#pragma unroll
            for (int i = 0; i < 4; i++) acc[mt][nt][i] = 0.0f;

    float4 aR[A_F4], bR[B_F4];

    auto fetch = [&](int j) {
#pragma unroll
        for (int t = 0; t < A_F4; t++)
            aR[t] = *(const float4*)&A[(size_t)(rowBase + ar[t]) * K + j * BK + akq[t]];
#pragma unroll
        for (int t = 0; t < B_F4; t++)
            bR[t] = *(const float4*)&B[(size_t)(j * BK + br[t]) * N + bc4[t]];
    };
    auto stage = [&](int buf) {
        float* Ab = As + buf * A_FLOATS;
        float* Bb = Bs + buf * B_FLOATS;
#pragma unroll
        for (int t = 0; t < A_F4; t++) {
            float4 v = aR[t];
            v.x = to_tf32(v.x); v.y = to_tf32(v.y); v.z = to_tf32(v.z); v.w = to_tf32(v.w);
            *(float4*)&Ab[ar[t] * AS + akq[t]] = v;
        }
#pragma unroll
        for (int t = 0; t < B_F4; t++) {
            float4 v = bR[t];
            v.x = to_tf32(v.x); v.y = to_tf32(v.y); v.z = to_tf32(v.z); v.w = to_tf32(v.w);
            *(float4*)&Bb[br[t] * BNS + bc4[t]] = v;
        }
    };

    fetch(0); stage(0);
    __syncthreads();

    for (int j = 0; j < NI; j++) {
        const int buf = j & 1;
        if (j + 1 < NI) fetch(j + 1);

        const float* Ab = As + buf * A_FLOATS;
        const float* Bb = Bs + buf * B_FLOATS;
#pragma unroll
        for (int kk = 0; kk < BK; kk += 8) {
            uint32_t afr[4][4];
#pragma unroll
            for (int mt = 0; mt < 4; mt++) {
                const int m0 = warpM * 64 + mt * 16;
                afr[mt][0] = __float_as_uint(Ab[(m0 + g    ) * AS + kk + qd    ]);
                afr[mt][1] = __float_as_uint(Ab[(m0 + g + 8) * AS + kk + qd    ]);
                afr[mt][2] = __float_as_uint(Ab[(m0 + g    ) * AS + kk + qd + 4]);
                afr[mt][3] = __float_as_uint(Ab[(m0 + g + 8) * AS + kk + qd + 4]);
            }
            uint32_t bfr[NT][2];
#pragma unroll
            for (int nt = 0; nt < NT; nt++) {
                const int n0 = warpN * WN + nt * 8;
                bfr[nt][0] = __float_as_uint(Bb[(kk + qd    ) * BNS + n0 + g]);
                bfr[nt][1] = __float_as_uint(Bb[(kk + qd + 4) * BNS + n0 + g]);
            }
#pragma unroll
            for (int mt = 0; mt < 4; mt++)
#pragma unroll
                for (int nt = 0; nt < NT; nt++)
                    mma_tf32(acc[mt][nt], afr[mt][0], afr[mt][1], afr[mt][2], afr[mt][3],
                             bfr[nt][0], bfr[nt][1]);
        }

        if (j + 1 < NI) {
            stage(buf ^ 1);
            __syncthreads();
        }
    }

    if (blockIdx.z == 0) {
#pragma unroll
        for (int mt = 0; mt < 4; mt++) {
            const int row0 = rowBase + warpM * 64 + mt * 16 + g;
#pragma unroll
            for (int nt = 0; nt < NT; nt++) {
                const int c = warpN * WN + nt * 8 + qd * 2;
                const float b0 = bias[c], b1 = bias[c + 1];
                float2 v0 = make_float2(acc[mt][nt][0] + b0, acc[mt][nt][1] + b1);
                float2 v1 = make_float2(acc[mt][nt][2] + b0, acc[mt][nt][3] + b1);
                *(float2*)&C[(size_t)row0 * N + c] = v0;
                *(float2*)&C[(size_t)(row0 + 8) * N + c] = v1;
            }
        }
    } else {
        auto wv = [&](int r, int n, float val) {
            int gt = r >> 6, rlo = r & 63;
            int p = ((rlo >> 3) << 2) | (rlo & 3);
            int comp = (rlo >> 2) & 1;
            C[(((size_t)gt * 32 + p) * 64 + n) * 2 + comp] = to_tf32(val);
        };
#pragma unroll
        for (int mt = 0; mt < 4; mt++) {
            const int row0 = rowBase + warpM * 64 + mt * 16 + g;
#pragma unroll
            for (int nt = 0; nt < NT; nt++) {
                const int c = warpN * WN + nt * 8 + qd * 2;
                const float b0 = bias[c], b1 = bias[c + 1];
                wv(row0,     c,     acc[mt][nt][0] + b0);
                wv(row0,     c + 1, acc[mt][nt][1] + b1);
                wv(row0 + 8, c,     acc[mt][nt][2] + b0);
                wv(row0 + 8, c + 1, acc[mt][nt][3] + b1);
            }
        }
    }
}

// =========================================================================
// RoPE: q in-place (natural); k natural -> paired-transposed tiles (tf32).
// =========================================================================
__global__ void rope_kernel(float* __restrict__ q, const float* __restrict__ kin,
                            float* __restrict__ k2out)
{
    const int total = BDIM*TDIM*(NH+1)*(HD/2);
    int idx = blockIdx.x*blockDim.x + threadIdx.x;
    if (idx >= total) return;
    int pr   = idx & 31;
    int rest = idx >> 5;
    int hh   = rest % (NH+1);
    int bt   = rest / (NH+1);
    int t    = bt & (TDIM-1);

    float inv_freq = expf(-(float)pr * (9.2103403719761836f / 32.0f));
    float ang = (float)t * inv_freq;
    float sn, cs;
    sincosf(ang, &sn, &cs);

    if (hh < NH) {
        float* base = q + (size_t)bt*CDIM + hh*HD;
        float t1 = base[pr];
        float t2 = base[pr + 32];
        base[pr]      = t1*cs + t2*sn;
        base[pr + 32] = t1*sn - t2*cs;
    } else {
        const float* base = kin + (size_t)bt*HD;
        float t1 = base[pr];
        float t2 = base[pr + 32];
        float v1 = t1*cs + t2*sn;
        float v2 = t1*sn - t2*cs;
        int gt = bt >> 6, c = bt & 63;
        int d1 = pr, d2 = pr + 32;
        int p1 = ((d1 >> 3) << 2) | (d1 & 3), c1 = (d1 >> 2) & 1;
        int p2 = ((d2 >> 3) << 2) | (d2 & 3), c2 = (d2 >> 2) & 1;
        k2out[(((size_t)gt*32 + p1)*64 + c)*2 + c1] = to_tf32(v1);
        k2out[(((size_t)gt*32 + p2)*64 + c)*2 + c2] = to_tf32(v2);
    }
}

// =========================================================================
// Tensor-core causal MQA flash attention (R8 structure, measured best).
// O-store writes PAIRED-K permutation + tf32 rounding for the Wo GEMM.
// =========================================================================
#define KP2S 68
#define QPS  68
#define TILE_F2 (32*KP2S)
#define BUF_F2  (2*TILE_F2)
#define ATT2_SMEM_BYTES (2*BUF_F2*8 + 64*QPS*4)   // 87040

__global__ void __launch_bounds__(128)
attn_tc_kernel(const float* __restrict__ gq, const float2* __restrict__ gk2,
               const float2* __restrict__ gv2, float* __restrict__ go)
{
    extern __shared__ float sm[];
    float*  QP  = sm + 2*BUF_F2*2;
    const uint32_t sbase = smem_u32(sm);

    const int qtile = (gridDim.x - 1) - blockIdx.x;   // heavy blocks first
    const int h     = blockIdx.y;
    const int b     = blockIdx.z;
    const int tid   = threadIdx.x;
    const int lane  = tid & 31;
    const int w     = tid >> 5;
    const int g     = lane >> 2;
    const int qd    = lane & 3;
    const int r0    = w * 16;
    const int qbase = qtile * 64;

    auto issue_tile = [&](int t, int buf) {
        const char* kgb = (const char*)(gk2 + (size_t)(b*32 + t) * 2048);
        const char* vgb = (const char*)(gv2 + (size_t)(b*32 + t) * 2048);
        const uint32_t kb = sbase + buf * (BUF_F2 * 8);
        const uint32_t vb = kb + TILE_F2 * 8;
#pragma unroll
        for (int i = 0; i < 8; i++) {
            int idx = tid + i * 128;
            int row = idx >> 5, ch = (idx & 31) << 4;
            CP_ASYNC16(kb + row * 544 + ch, kgb + row * 512 + ch);
            CP_ASYNC16(vb + row * 544 + ch, vgb + row * 512 + ch);
        }
        CP_COMMIT();
    };

    issue_tile(0, 0);

    {
        const float* qp = gq + ((size_t)(b*TDIM + qbase))*CDIM + h*HD;
#pragma unroll
        for (int i = 0; i < 8; i++) {
            int idx = tid + i*128;
            int r = idx >> 4, d4 = (idx & 15) << 2;
            float4 v = *(const float4*)(qp + (size_t)r*CDIM + d4);
            QP[r*QPS + d4+0] = to_tf32(v.x*0.125f);
            QP[r*QPS + d4+1] = to_tf32(v.y*0.125f);
            QP[r*QPS + d4+2] = to_tf32(v.z*0.125f);
            QP[r*QPS + d4+3] = to_tf32(v.w*0.125f);
        }
    }
    __syncthreads();

    uint32_t aQ[8][4];
#pragma unroll
    for (int kk = 0; kk < 8; kk++) {
        const int kb = kk*8;
        aQ[kk][0] = __float_as_uint(QP[(r0+g  )*QPS + kb + qd    ]);
        aQ[kk][1] = __float_as_uint(QP[(r0+g+8)*QPS + kb + qd    ]);
        aQ[kk][2] = __float_as_uint(QP[(r0+g  )*QPS + kb + qd + 4]);
        aQ[kk][3] = __float_as_uint(QP[(r0+g+8)*QPS + kb + qd + 4]);
    }

    float m_[2] = {-1e30f, -1e30f};
    float l_[2] = {0.0f, 0.0f};
    float oacc[8][4];
#pragma unroll
    for (int nt = 0; nt < 8; nt++)
#pragma unroll
        for (int i = 0; i < 4; i++) oacc[nt][i] = 0.0f;

    for (int t = 0; t <= qtile; t++) {
        const int buf = t & 1;

        CP_WAIT0();
        __syncthreads();

        if (t < qtile) issue_tile(t + 1, buf ^ 1);

        const float2* KtP = (const float2*)sm + (size_t)buf * BUF_F2;
        const float2* VsP = KtP + TILE_F2;

        float sacc[8][4];
#pragma unroll
        for (int nt = 0; nt < 8; nt++)
#pragma unroll
            for (int i = 0; i < 4; i++) sacc[nt][i] = 0.0f;

#pragma unroll
        for (int kk = 0; kk < 8; kk++) {
            float2 bf[8];
#pragma unroll
            for (int nt = 0; nt < 8; nt++)
                bf[nt] = KtP[(kk*4+qd)*KP2S + nt*8 + g];
#pragma unroll
            for (int nt = 0; nt < 8; nt++)
                mma_tf32(sacc[nt], aQ[kk][0], aQ[kk][1], aQ[kk][2], aQ[kk][3],
                         __float_as_uint(bf[nt].x), __float_as_uint(bf[nt].y));
        }

        if (t == qtile) {
            const int ra = r0 + g, rb = ra + 8;
#pragma unroll
            for (int nt = 0; nt < 8; nt++) {
                const int ca = nt*8 + qd*2;
                if (ca     > ra) sacc[nt][0] = -1e30f;
                if (ca + 1 > ra) sacc[nt][1] = -1e30f;
                if (ca     > rb) sacc[nt][2] = -1e30f;
                if (ca + 1 > rb) sacc[nt][3] = -1e30f;
            }
        }

#pragma unroll
        for (int rr = 0; rr < 2; rr++) {
            float lm = -1e30f;
#pragma unroll
            for (int nt = 0; nt < 8; nt++)
                lm = fmaxf(lm, fmaxf(sacc[nt][2*rr], sacc[nt][2*rr+1]));
            lm = fmaxf(lm, __shfl_xor_sync(0xffffffffu, lm, 1));
            lm = fmaxf(lm, __shfl_xor_sync(0xffffffffu, lm, 2));
            float mnew  = fmaxf(m_[rr], lm);
            float alpha = __expf(m_[rr] - mnew);

            float ls = 0.0f;
#pragma unroll
            for (int nt = 0; nt < 8; nt++) {
                float p0 = __expf(sacc[nt][2*rr]   - mnew);
                float p1 = __expf(sacc[nt][2*rr+1] - mnew);
                ls += p0 + p1;
                *(float2*)&QP[(r0 + g + rr*8)*QPS + nt*8 + qd*2] =
                    make_float2(to_tf32(p0), to_tf32(p1));
            }
            ls += __shfl_xor_sync(0xffffffffu, ls, 1);
            ls += __shfl_xor_sync(0xffffffffu, ls, 2);

            m_[rr] = mnew;
            l_[rr] = l_[rr]*alpha + ls;
#pragma unroll
            for (int nt = 0; nt < 8; nt++) {
                oacc[nt][2*rr]   *= alpha;
                oacc[nt][2*rr+1] *= alpha;
            }
        }
        __syncwarp();

#pragma unroll
        for (int kk = 0; kk < 8; kk++) {
            const int kb = kk*8;
            uint32_t pa0 = __float_as_uint(QP[(r0+g  )*QPS + kb + qd    ]);
            uint32_t pa1 = __float_as_uint(QP[(r0+g+8)*QPS + kb + qd    ]);
            uint32_t pa2 = __float_as_uint(QP[(r0+g  )*QPS + kb + qd + 4]);
            uint32_t pa3 = __float_as_uint(QP[(r0+g+8)*QPS + kb + qd + 4]);
            float2 bv[8];
#pragma unroll
            for (int nt = 0; nt < 8; nt++)
                bv[nt] = VsP[(kk*4+qd)*KP2S + nt*8 + g];
#pragma unroll
            for (int nt = 0; nt < 8; nt++)
                mma_tf32(oacc[nt], pa0, pa1, pa2, pa3,
                         __float_as_uint(bv[nt].x), __float_as_uint(bv[nt].y));
        }
        __syncwarp();
    }

    // ---- normalize + store in PAIRED-K permutation (tf32-rounded) ----
    // col 2qd   -> pos p0 = ((qd&1)<<2)|(qd>>1);  col 2qd+1 -> p0+2
    const int p0 = ((qd & 1) << 2) | (qd >> 1);
#pragma unroll
    for (int rr = 0; rr < 2; rr++) {
        const float inv = 1.0f / l_[rr];
        float* op = go + ((size_t)(b*TDIM + qbase + r0 + g + rr*8))*CDIM + h*HD;
#pragma unroll
        for (int nt = 0; nt < 8; nt++) {
            op[nt*8 + p0    ] = to_tf32(oacc[nt][2*rr]   * inv);
            op[nt*8 + p0 + 2] = to_tf32(oacc[nt][2*rr+1] * inv);
        }
    }
}

// =========================================================================
// launch
// =========================================================================
extern "C" void kernel_launch(void* const* d_in, const int* in_sizes, int n_in,
                              void* d_out, int out_size)
{
    const float* x  = (const float*)d_in[0];
    const float* Wq = (const float*)d_in[1];
    const float* bq = (const float*)d_in[2];
    const float* Wk = (const float*)d_in[3];
    const float* bk = (const float*)d_in[4];
    const float* Wv = (const float*)d_in[5];
    const float* bv = (const float*)d_in[6];
    const float* Wo = (const float*)d_in[7];
    const float* bo = (const float*)d_in[8];
    float* out = (float*)d_out;

    float *qp, *kp, *k2p, *vp, *ap, *xr, *wqr, *wor;
    cudaGetSymbolAddress((void**)&qp,  g_q);
    cudaGetSymbolAddress((void**)&kp,  g_k);
    cudaGetSymbolAddress((void**)&k2p, g_k2);
    cudaGetSymbolAddress((void**)&vp,  g_v);
    cudaGetSymbolAddress((void**)&ap,  g_att);
    cudaGetSymbolAddress((void**)&xr,  g_xr);
    cudaGetSymbolAddress((void**)&wqr, g_wqr);
    cudaGetSymbolAddress((void**)&wor, g_wor);

    constexpr int SM64 = (2*(128*20) + 2*(16*72)) * 4;   // 29696 B
    cudaFuncSetAttribute(tc_gemm_pipe2_kernel,
        cudaFuncAttributeMaxDynamicSharedMemorySize, G2_SMEM);
    cudaFuncSetAttribute(tc_gemm_kv_kernel,
        cudaFuncAttributeMaxDynamicSharedMemorySize, SM64);
    cudaFuncSetAttribute(attn_tc_kernel,
        cudaFuncAttributeMaxDynamicSharedMemorySize, ATT2_SMEM_BYTES);

    // operand prep: x paired-K; Wq/Wo row-paired (all tf32-RNA)
    {
        int ngx = MROWS*CDIM/8;
        pairK_round_kernel<<<(ngx + 255)/256, 256>>>((const float4*)x, (float4*)xr, ngx);
        pairB_round_kernel<<<(128*4*256 + 255)/256, 256>>>(Wq, (float4*)wqr);
        pairB_round_kernel<<<(128*4*256 + 255)/256, 256>>>(Wo, (float4*)wor);
    }

    // Q = x @ Wq + bq   (BM=256, single-wave grid, paired operands)
    tc_gemm_pipe2_kernel<<<dim3(CDIM/128, MROWS/256), 256, G2_SMEM>>>(
        xr, wqr, bq, qp, MROWS, CDIM, CDIM);
    // K (natural), V (paired) fused
    tc_gemm_kv_kernel<<<dim3(1, MROWS/128, 2), 256, SM64>>>(
        x, Wk, bk, kp, Wv, bv, vp, MROWS, HD, CDIM);

    // RoPE: q in-place, k natural -> paired
    {
        int total = BDIM*TDIM*(NH+1)*(HD/2);
        rope_kernel<<<(total + 255)/256, 256>>>(qp, kp, k2p);
    }

    // causal MQA attention (R8 structure; O stored paired-K + rounded)
    attn_tc_kernel<<<dim3(TDIM/64, NH, BDIM), 128, ATT2_SMEM_BYTES>>>(
        qp, (const float2*)k2p, (const float2*)vp, ap);

    // out = att @ Wo + bo
    tc_gemm_pipe2_kernel<<<dim3(CDIM/128, MROWS/256), 256, G2_SMEM>>>(
        ap, wor, bo, out, MROWS, CDIM, CDIM);
}

// round 11
// speedup vs baseline: 1.3025x; 1.3025x over previous
#include <cuda_runtime.h>
#include <math.h>
#include <cstdint>

// Problem dims (fixed)
#define BDIM 2
#define TDIM 2048
#define CDIM 1024
#define NH   16
#define HD   64
#define MROWS (BDIM*TDIM)   // 4096

// ---------------- device scratch (no allocations allowed) ----------------
__device__ float g_q[(size_t)MROWS*CDIM];   // q after rope (natural layout)
__device__ float g_k[(size_t)MROWS*HD];     // k pre-rope (natural, gemm out)
__device__ float g_k2[(size_t)MROWS*HD];    // k post-rope, paired-transposed tiles
__device__ float g_v[(size_t)MROWS*HD];     // v paired tiles (gemm writes directly)
__device__ float g_att[(size_t)MROWS*CDIM]; // attn out, tf32-prerounded (natural)
__device__ float g_xr[(size_t)MROWS*CDIM];  // x  tf32-prerounded
__device__ float g_wqr[(size_t)CDIM*CDIM];  // Wq tf32-prerounded
__device__ float g_wor[(size_t)CDIM*CDIM];  // Wo tf32-prerounded

// ======================= helpers =========================================
__device__ __forceinline__ float to_tf32(float x) {
    float r; asm("cvt.rna.tf32.f32 %0, %1;" : "=f"(r) : "f"(x)); return r;
}
__device__ __forceinline__ void mma_tf32(float* c,
    uint32_t a0, uint32_t a1, uint32_t a2, uint32_t a3,
    uint32_t b0, uint32_t b1)
{
    asm volatile(
        "mma.sync.aligned.m16n8k8.row.col.f32.tf32.tf32.f32 "
        "{%0,%1,%2,%3}, {%4,%5,%6,%7}, {%8,%9}, {%0,%1,%2,%3};"
        : "+f"(c[0]), "+f"(c[1]), "+f"(c[2]), "+f"(c[3])
        : "r"(a0), "r"(a1), "r"(a2), "r"(a3), "r"(b0), "r"(b1));
}
__device__ __forceinline__ uint32_t smem_u32(const void* p) {
    uint32_t a;
    asm("{ .reg .u64 t; cvta.to.shared.u64 t, %1; cvt.u32.u64 %0, t; }"
        : "=r"(a) : "l"(p));
    return a;
}
#define CP_ASYNC16(dst_u32, src_ptr) \
    asm volatile("cp.async.cg.shared.global [%0], [%1], 16;" \
        :: "r"(dst_u32), "l"(src_ptr) : "memory")
#define CP_COMMIT() asm volatile("cp.async.commit_group;" ::: "memory")
#define CP_WAIT0()  asm volatile("cp.async.wait_group 0;"  ::: "memory")
#define CP_WAIT1()  asm volatile("cp.async.wait_group 1;"  ::: "memory")

// =========================================================================
// tf32 round-copy (RNA): out[i] = tf32(in[i]); n multiple of 4.
// =========================================================================
__global__ void round4_kernel(const float4* __restrict__ in,
                              float4* __restrict__ out, int n4)
{
    int i = blockIdx.x * blockDim.x + threadIdx.x;
    if (i >= n4) return;
    float4 v = in[i];
    v.x = to_tf32(v.x); v.y = to_tf32(v.y); v.z = to_tf32(v.z); v.w = to_tf32(v.w);
    out[i] = v;
}

// =========================================================================
// 3-stage cp.async pipelined tf32 GEMM (inputs PRE-ROUNDED to tf32):
//   C[M,N] = A[M,K] @ B[K,N] + bias[N]
// BM=128, BN=128, BK=16, 256 threads = 8 warps (2m x 4n).   [R9, measured]
// =========================================================================
#define GP_AS  20
#define GP_BNS 136
#define GP_AST (128*GP_AS)          // 2560 floats
#define GP_BST (16*GP_BNS)          // 2176 floats
#define GP_STF (GP_AST+GP_BST)      // 4736 floats per stage
#define GP_SMEM (3*GP_STF*4)        // 56832 bytes

__global__ void __launch_bounds__(256)
tc_gemm_pipe_kernel(const float* __restrict__ A, const float* __restrict__ B,
                    const float* __restrict__ bias, float* __restrict__ C,
                    int M, int N, int K)
{
    constexpr int BK = 16;
    extern __shared__ float sm[];
    const uint32_t sbase = smem_u32(sm);

    const int tid   = threadIdx.x;
    const int lane  = tid & 31;
    const int w     = tid >> 5;
    const int warpM = w & 1;
    const int warpN = w >> 1;
    const int g     = lane >> 2;
    const int qd    = lane & 3;
    const int rowBase = blockIdx.y * 128;
    const int colBase = blockIdx.x * 128;

    // 4 cp.async 16B chunks per thread per stage (A: 512 chunks, B: 512)
    const float* gsrc[4]; uint32_t soff[4]; size_t jstr[4];
#pragma unroll
    for (int i = 0; i < 4; i++) {
        int idx = tid + i * 256;
        if (idx < 512) {
            int r = idx >> 2, c4 = (idx & 3) * 4;
            gsrc[i] = A + (size_t)(rowBase + r) * K + c4;
            soff[i] = (uint32_t)(r * GP_AS + c4) * 4;
            jstr[i] = BK;
        } else {
            int e = idx - 512;
            int r = e >> 5, c4 = (e & 31) * 4;
            gsrc[i] = B + (size_t)r * N + colBase + c4;
            soff[i] = (uint32_t)(GP_AST + r * GP_BNS + c4) * 4;
            jstr[i] = (size_t)BK * N;
        }
    }
    auto issue = [&](int j, int s) {
        const uint32_t sb = sbase + (uint32_t)s * (GP_STF * 4);
#pragma unroll
        for (int i = 0; i < 4; i++)
            CP_ASYNC16(sb + soff[i], gsrc[i] + (size_t)j * jstr[i]);
        CP_COMMIT();
    };

    const int NI = K / BK;   // 64

    float acc[4][4][4];
#pragma unroll
    for (int mt = 0; mt < 4; mt++)
#pragma unroll
        for (int nt = 0; nt < 4; nt++)
#pragma unroll
            for (int i = 0; i < 4; i++) acc[mt][nt][i] = 0.0f;

    issue(0, 0);
    issue(1, 1);

    int s = 0;
    for (int j = 0; j < NI; j++) {
        CP_WAIT1();
        __syncthreads();

        if (j + 2 < NI) {
            int s2 = s + 2; if (s2 >= 3) s2 -= 3;
            issue(j + 2, s2);
        } else {
            CP_COMMIT();   // empty group keeps wait_group accounting aligned
        }

        const float* Ab = sm + s * GP_STF;
        const float* Bb = Ab + GP_AST;
#pragma unroll
        for (int kk = 0; kk < BK; kk += 8) {
            uint32_t afr[4][4];
#pragma unroll
            for (int mt = 0; mt < 4; mt++) {
                const int m0 = warpM * 64 + mt * 16;
                afr[mt][0] = __float_as_uint(Ab[(m0 + g    ) * GP_AS + kk + qd    ]);
                afr[mt][1] = __float_as_uint(Ab[(m0 + g + 8) * GP_AS + kk + qd    ]);
                afr[mt][2] = __float_as_uint(Ab[(m0 + g    ) * GP_AS + kk + qd + 4]);
                afr[mt][3] = __float_as_uint(Ab[(m0 + g + 8) * GP_AS + kk + qd + 4]);
            }
            uint32_t bfr[4][2];
#pragma unroll
            for (int nt = 0; nt < 4; nt++) {
                const int n0 = warpN * 32 + nt * 8;
                bfr[nt][0] = __float_as_uint(Bb[(kk + qd    ) * GP_BNS + n0 + g]);
                bfr[nt][1] = __float_as_uint(Bb[(kk + qd + 4) * GP_BNS + n0 + g]);
            }
#pragma unroll
            for (int mt = 0; mt < 4; mt++)
#pragma unroll
                for (int nt = 0; nt < 4; nt++)
                    mma_tf32(acc[mt][nt], afr[mt][0], afr[mt][1], afr[mt][2], afr[mt][3],
                             bfr[nt][0], bfr[nt][1]);
        }
        if (++s == 3) s = 0;
    }

#pragma unroll
    for (int mt = 0; mt < 4; mt++) {
        const int row0 = rowBase + warpM * 64 + mt * 16 + g;
#pragma unroll
        for (int nt = 0; nt < 4; nt++) {
            const int c = colBase + warpN * 32 + nt * 8 + qd * 2;
            const float b0 = bias[c], b1 = bias[c + 1];
            float2 v0 = make_float2(acc[mt][nt][0] + b0, acc[mt][nt][1] + b1);
            float2 v1 = make_float2(acc[mt][nt][2] + b0, acc[mt][nt][3] + b1);
            *(float2*)&C[(size_t)row0 * N + c] = v0;
            *(float2*)&C[(size_t)(row0 + 8) * N + c] = v1;
        }
    }
}

// =========================================================================
// K and V projections fused: z=0 -> K natural, z=1 -> V paired tiles.
// =========================================================================
__global__ void __launch_bounds__(256)
tc_gemm_kv_kernel(const float* __restrict__ A,
                  const float* __restrict__ B0, const float* __restrict__ bias0,
                  float* __restrict__ C0,
                  const float* __restrict__ B1, const float* __restrict__ bias1,
                  float* __restrict__ C1,
                  int M, int N, int K)
{
    constexpr int BN  = 64;
    constexpr int BM  = 128;
    constexpr int BK  = 16;
    constexpr int AS  = BK + 4;
    constexpr int BNS = BN + 8;
    constexpr int A_FLOATS = BM * AS;
    constexpr int B_FLOATS = BK * BNS;
    constexpr int A_F4 = BM * BK / (4 * 256);
    constexpr int B_F4 = BK * BN / (4 * 256);
    constexpr int NT   = BN / 32;
    constexpr int WN   = BN / 4;

    const float* B    = blockIdx.z ? B1 : B0;
    const float* bias = blockIdx.z ? bias1 : bias0;
    float*       C    = blockIdx.z ? C1 : C0;

    extern __shared__ float sm[];
    float* As = sm;
    float* Bs = sm + 2 * A_FLOATS;

    const int tid   = threadIdx.x;
    const int lane  = tid & 31;
    const int w     = tid >> 5;
    const int warpM = w & 1;
    const int warpN = w >> 1;
    const int g     = lane >> 2;
    const int qd    = lane & 3;
    const int rowBase = blockIdx.y * BM;

    int ar[A_F4]; int akq[A_F4];
#pragma unroll
    for (int t = 0; t < A_F4; t++) {
        int idx = tid + t * 256;
        ar[t] = idx >> 2; akq[t] = (idx & 3) * 4;
    }
    int br[B_F4]; int bc4[B_F4];
#pragma unroll
    for (int t = 0; t < B_F4; t++) {
        int idx = tid + t * 256;
        br[t] = idx / (BN / 4); bc4[t] = (idx % (BN / 4)) * 4;
    }

    const int NI = K / BK;

    float acc[4][NT][4];
#pragma unroll
    for (int mt = 0; mt < 4; mt++)
#pragma unroll
        for (int nt = 0; nt < NT; nt++)
#pragma unroll
            for (int i = 0; i < 4; i++) acc[mt][nt][i] = 0.0f;

    float4 aR[A_F4], bR[B_F4];

    auto fetch = [&](int j) {
#pragma unroll
        for (int t = 0; t < A_F4; t++)
            aR[t] = *(const float4*)&A[(size_t)(rowBase + ar[t]) * K + j * BK + akq[t]];
#pragma unroll
        for (int t = 0; t < B_F4; t++)
            bR[t] = *(const float4*)&B[(size_t)(j * BK + br[t]) * N + bc4[t]];
    };
    auto stage = [&](int buf) {
        float* Ab = As + buf * A_FLOATS;
        float* Bb = Bs + buf * B_FLOATS;
#pragma unroll
        for (int t = 0; t < A_F4; t++) {
            float4 v = aR[t];
            v.x = to_tf32(v.x); v.y = to_tf32(v.y); v.z = to_tf32(v.z); v.w = to_tf32(v.w);
            *(float4*)&Ab[ar[t] * AS + akq[t]] = v;
        }
#pragma unroll
        for (int t = 0; t < B_F4; t++) {
            float4 v = bR[t];
            v.x = to_tf32(v.x); v.y = to_tf32(v.y); v.z = to_tf32(v.z); v.w = to_tf32(v.w);
            *(float4*)&Bb[br[t] * BNS + bc4[t]] = v;
        }
    };

    fetch(0); stage(0);
    __syncthreads();

    for (int j = 0; j < NI; j++) {
        const int buf = j & 1;
        if (j + 1 < NI) fetch(j + 1);

        const float* Ab = As + buf * A_FLOATS;
        const float* Bb = Bs + buf * B_FLOATS;
#pragma unroll
        for (int kk = 0; kk < BK; kk += 8) {
            uint32_t afr[4][4];
#pragma unroll
            for (int mt = 0; mt < 4; mt++) {
                const int m0 = warpM * 64 + mt * 16;
                afr[mt][0] = __float_as_uint(Ab[(m0 + g    ) * AS + kk + qd    ]);
                afr[mt][1] = __float_as_uint(Ab[(m0 + g + 8) * AS + kk + qd    ]);
                afr[mt][2] = __float_as_uint(Ab[(m0 + g    ) * AS + kk + qd + 4]);
                afr[mt][3] = __float_as_uint(Ab[(m0 + g + 8) * AS + kk + qd + 4]);
            }
            uint32_t bfr[NT][2];
#pragma unroll
            for (int nt = 0; nt < NT; nt++) {
                const int n0 = warpN * WN + nt * 8;
                bfr[nt][0] = __float_as_uint(Bb[(kk + qd    ) * BNS + n0 + g]);
                bfr[nt][1] = __float_as_uint(Bb[(kk + qd + 4) * BNS + n0 + g]);
            }
#pragma unroll
            for (int mt = 0; mt < 4; mt++)
#pragma unroll
                for (int nt = 0; nt < NT; nt++)
                    mma_tf32(acc[mt][nt], afr[mt][0], afr[mt][1], afr[mt][2], afr[mt][3],
                             bfr[nt][0], bfr[nt][1]);
        }

        if (j + 1 < NI) {
            stage(buf ^ 1);
            __syncthreads();
        }
    }

    if (blockIdx.z == 0) {
#pragma unroll
        for (int mt = 0; mt < 4; mt++) {
            const int row0 = rowBase + warpM * 64 + mt * 16 + g;
#pragma unroll
            for (int nt = 0; nt < NT; nt++) {
                const int c = warpN * WN + nt * 8 + qd * 2;
                const float b0 = bias[c], b1 = bias[c + 1];
                float2 v0 = make_float2(acc[mt][nt][0] + b0, acc[mt][nt][1] + b1);
                float2 v1 = make_float2(acc[mt][nt][2] + b0, acc[mt][nt][3] + b1);
                *(float2*)&C[(size_t)row0 * N + c] = v0;
                *(float2*)&C[(size_t)(row0 + 8) * N + c] = v1;
            }
        }
    } else {
        auto wv = [&](int r, int n, float val) {
            int gt = r >> 6, rlo = r & 63;
            int p = ((rlo >> 3) << 2) | (rlo & 3);
            int comp = (rlo >> 2) & 1;
            C[(((size_t)gt * 32 + p) * 64 + n) * 2 + comp] = to_tf32(val);
        };
#pragma unroll
        for (int mt = 0; mt < 4; mt++) {
            const int row0 = rowBase + warpM * 64 + mt * 16 + g;
#pragma unroll
            for (int nt = 0; nt < NT; nt++) {
                const int c = warpN * WN + nt * 8 + qd * 2;
                const float b0 = bias[c], b1 = bias[c + 1];
                wv(row0,     c,     acc[mt][nt][0] + b0);
                wv(row0,     c + 1, acc[mt][nt][1] + b1);
                wv(row0 + 8, c,     acc[mt][nt][2] + b0);
                wv(row0 + 8, c + 1, acc[mt][nt][3] + b1);
            }
        }
    }
}

// =========================================================================
// RoPE: q in-place (natural); k natural -> paired-transposed tiles (tf32).
// =========================================================================
__global__ void rope_kernel(float* __restrict__ q, const float* __restrict__ kin,
                            float* __restrict__ k2out)
{
    const int total = BDIM*TDIM*(NH+1)*(HD/2);
    int idx = blockIdx.x*blockDim.x + threadIdx.x;
    if (idx >= total) return;
    int pr   = idx & 31;
    int rest = idx >> 5;
    int hh   = rest % (NH+1);
    int bt   = rest / (NH+1);
    int t    = bt & (TDIM-1);

    float inv_freq = expf(-(float)pr * (9.2103403719761836f / 32.0f));
    float ang = (float)t * inv_freq;
    float sn, cs;
    sincosf(ang, &sn, &cs);

    if (hh < NH) {
        float* base = q + (size_t)bt*CDIM + hh*HD;
        float t1 = base[pr];
        float t2 = base[pr + 32];
        base[pr]      = t1*cs + t2*sn;
        base[pr + 32] = t1*sn - t2*cs;
    } else {
        const float* base = kin + (size_t)bt*HD;
        float t1 = base[pr];
        float t2 = base[pr + 32];
        float v1 = t1*cs + t2*sn;
        float v2 = t1*sn - t2*cs;
        int gt = bt >> 6, c = bt & 63;
        int d1 = pr, d2 = pr + 32;
        int p1 = ((d1 >> 3) << 2) | (d1 & 3), c1 = (d1 >> 2) & 1;
        int p2 = ((d2 >> 3) << 2) | (d2 & 3), c2 = (d2 >> 2) & 1;
        k2out[(((size_t)gt*32 + p1)*64 + c)*2 + c1] = to_tf32(v1);
        k2out[(((size_t)gt*32 + p2)*64 + c)*2 + c2] = to_tf32(v2);
    }
}

// =========================================================================
// Tensor-core causal MQA flash attention (R8 version — measured best).
// Output: natural layout float2 stores, tf32-rounded for the Wo GEMM.
// =========================================================================
#define KP2S 68
#define QPS  68
#define TILE_F2 (32*KP2S)
#define BUF_F2  (2*TILE_F2)
#define ATT2_SMEM_BYTES (2*BUF_F2*8 + 64*QPS*4)   // 87040

__global__ void __launch_bounds__(128)
attn_tc_kernel(const float* __restrict__ gq, const float2* __restrict__ gk2,
               const float2* __restrict__ gv2, float* __restrict__ go)
{
    extern __shared__ float sm[];
    float*  QP  = sm + 2*BUF_F2*2;
    const uint32_t sbase = smem_u32(sm);

    const int qtile = (gridDim.x - 1) - blockIdx.x;   // heavy blocks first
    const int h     = blockIdx.y;
    const int b     = blockIdx.z;
    const int tid   = threadIdx.x;
    const int lane  = tid & 31;
    const int w     = tid >> 5;
    const int g     = lane >> 2;
    const int qd    = lane & 3;
    const int r0    = w * 16;
    const int qbase = qtile * 64;

    auto issue_tile = [&](int t, int buf) {
        const char* kgb = (const char*)(gk2 + (size_t)(b*32 + t) * 2048);
        const char* vgb = (const char*)(gv2 + (size_t)(b*32 + t) * 2048);
        const uint32_t kb = sbase + buf * (BUF_F2 * 8);
        const uint32_t vb = kb + TILE_F2 * 8;
#pragma unroll
        for (int i = 0; i < 8; i++) {
            int idx = tid + i * 128;
            int row = idx >> 5, ch = (idx & 31) << 4;
            CP_ASYNC16(kb + row * 544 + ch, kgb + row * 512 + ch);
            CP_ASYNC16(vb + row * 544 + ch, vgb + row * 512 + ch);
        }
        CP_COMMIT();
    };

    issue_tile(0, 0);

    {
        const float* qp = gq + ((size_t)(b*TDIM + qbase))*CDIM + h*HD;
#pragma unroll
        for (int i = 0; i < 8; i++) {
            int idx = tid + i*128;
            int r = idx >> 4, d4 = (idx & 15) << 2;
            float4 v = *(const float4*)(qp + (size_t)r*CDIM + d4);
            QP[r*QPS + d4+0] = to_tf32(v.x*0.125f);
            QP[r*QPS + d4+1] = to_tf32(v.y*0.125f);
            QP[r*QPS + d4+2] = to_tf32(v.z*0.125f);
            QP[r*QPS + d4+3] = to_tf32(v.w*0.125f);
        }
    }
    __syncthreads();

    uint32_t aQ[8][4];
#pragma unroll
    for (int kk = 0; kk < 8; kk++) {
        const int kb = kk*8;
        aQ[kk][0] = __float_as_uint(QP[(r0+g  )*QPS + kb + qd    ]);
        aQ[kk][1] = __float_as_uint(QP[(r0+g+8)*QPS + kb + qd    ]);
        aQ[kk][2] = __float_as_uint(QP[(r0+g  )*QPS + kb + qd + 4]);
        aQ[kk][3] = __float_as_uint(QP[(r0+g+8)*QPS + kb + qd + 4]);
    }

    float m_[2] = {-1e30f, -1e30f};
    float l_[2] = {0.0f, 0.0f};
    float oacc[8][4];
#pragma unroll
    for (int nt = 0; nt < 8; nt++)
#pragma unroll
        for (int i = 0; i < 4; i++) oacc[nt][i] = 0.0f;

    for (int t = 0; t <= qtile; t++) {
        const int buf = t & 1;

        CP_WAIT0();
        __syncthreads();

        if (t < qtile) issue_tile(t + 1, buf ^ 1);

        const float2* KtP = (const float2*)sm + (size_t)buf * BUF_F2;
        const float2* VsP = KtP + TILE_F2;

        float sacc[8][4];
#pragma unroll
        for (int nt = 0; nt < 8; nt++)
#pragma unroll
            for (int i = 0; i < 4; i++) sacc[nt][i] = 0.0f;

#pragma unroll
        for (int kk = 0; kk < 8; kk++) {
            float2 bf[8];
#pragma unroll
            for (int nt = 0; nt < 8; nt++)
                bf[nt] = KtP[(kk*4+qd)*KP2S + nt*8 + g];
#pragma unroll
            for (int nt = 0; nt < 8; nt++)
                mma_tf32(sacc[nt], aQ[kk][0], aQ[kk][1], aQ[kk][2], aQ[kk][3],
                         __float_as_uint(bf[nt].x), __float_as_uint(bf[nt].y));
        }

        if (t == qtile) {
            const int ra = r0 + g, rb = ra + 8;
#pragma unroll
            for (int nt = 0; nt < 8; nt++) {
                const int ca = nt*8 + qd*2;
                if (ca     > ra) sacc[nt][0] = -1e30f;
                if (ca + 1 > ra) sacc[nt][1] = -1e30f;
                if (ca     > rb) sacc[nt][2] = -1e30f;
                if (ca + 1 > rb) sacc[nt][3] = -1e30f;
            }
        }

#pragma unroll
        for (int rr = 0; rr < 2; rr++) {
            float lm = -1e30f;
#pragma unroll
            for (int nt = 0; nt < 8; nt++)
                lm = fmaxf(lm, fmaxf(sacc[nt][2*rr], sacc[nt][2*rr+1]));
            lm = fmaxf(lm, __shfl_xor_sync(0xffffffffu, lm, 1));
            lm = fmaxf(lm, __shfl_xor_sync(0xffffffffu, lm, 2));
            float mnew  = fmaxf(m_[rr], lm);
            float alpha = __expf(m_[rr] - mnew);

            float ls = 0.0f;
#pragma unroll
            for (int nt = 0; nt < 8; nt++) {
                float p0 = __expf(sacc[nt][2*rr]   - mnew);
                float p1 = __expf(sacc[nt][2*rr+1] - mnew);
                ls += p0 + p1;
                *(float2*)&QP[(r0 + g + rr*8)*QPS + nt*8 + qd*2] =
                    make_float2(to_tf32(p0), to_tf32(p1));
            }
            ls += __shfl_xor_sync(0xffffffffu, ls, 1);
            ls += __shfl_xor_sync(0xffffffffu, ls, 2);

            m_[rr] = mnew;
            l_[rr] = l_[rr]*alpha + ls;
#pragma unroll
            for (int nt = 0; nt < 8; nt++) {
                oacc[nt][2*rr]   *= alpha;
                oacc[nt][2*rr+1] *= alpha;
            }
        }
        __syncwarp();

#pragma unroll
        for (int kk = 0; kk < 8; kk++) {
            const int kb = kk*8;
            uint32_t pa0 = __float_as_uint(QP[(r0+g  )*QPS + kb + qd    ]);
            uint32_t pa1 = __float_as_uint(QP[(r0+g+8)*QPS + kb + qd    ]);
            uint32_t pa2 = __float_as_uint(QP[(r0+g  )*QPS + kb + qd + 4]);
            uint32_t pa3 = __float_as_uint(QP[(r0+g+8)*QPS + kb + qd + 4]);
            float2 bv[8];
#pragma unroll
            for (int nt = 0; nt < 8; nt++)
                bv[nt] = VsP[(kk*4+qd)*KP2S + nt*8 + g];
#pragma unroll
            for (int nt = 0; nt < 8; nt++)
                mma_tf32(oacc[nt], pa0, pa1, pa2, pa3,
                         __float_as_uint(bv[nt].x), __float_as_uint(bv[nt].y));
        }
        __syncwarp();
    }

    // ---- normalize + store (tf32-prerounded, natural layout) ----
#pragma unroll
    for (int rr = 0; rr < 2; rr++) {
        const float inv = 1.0f / l_[rr];
        float* op = go + ((size_t)(b*TDIM + qbase + r0 + g + rr*8))*CDIM + h*HD;
#pragma unroll
        for (int nt = 0; nt < 8; nt++) {
            *(float2*)&op[nt*8 + qd*2] =
                make_float2(to_tf32(oacc[nt][2*rr]*inv), to_tf32(oacc[nt][2*rr+1]*inv));
        }
    }
}

// =========================================================================
// launch
// =========================================================================
extern "C" void kernel_launch(void* const* d_in, const int* in_sizes, int n_in,
                              void* d_out, int out_size)
{
    const float* x  = (const float*)d_in[0];
    const float* Wq = (const float*)d_in[1];
    const float* bq = (const float*)d_in[2];
    const float* Wk = (const float*)d_in[3];
    const float* bk = (const float*)d_in[4];
    const float* Wv = (const float*)d_in[5];
    const float* bv = (const float*)d_in[6];
    const float* Wo = (const float*)d_in[7];
    const float* bo = (const float*)d_in[8];
    float* out = (float*)d_out;

    float *qp, *kp, *k2p, *vp, *ap, *xr, *wqr, *wor;
    cudaGetSymbolAddress((void**)&qp,  g_q);
    cudaGetSymbolAddress((void**)&kp,  g_k);
    cudaGetSymbolAddress((void**)&k2p, g_k2);
    cudaGetSymbolAddress((void**)&vp,  g_v);
    cudaGetSymbolAddress((void**)&ap,  g_att);
    cudaGetSymbolAddress((void**)&xr,  g_xr);
    cudaGetSymbolAddress((void**)&wqr, g_wqr);
    cudaGetSymbolAddress((void**)&wor, g_wor);

    constexpr int SM64 = (2*(128*20) + 2*(16*72)) * 4;   // 29696 B
    cudaFuncSetAttribute(tc_gemm_pipe_kernel,
        cudaFuncAttributeMaxDynamicSharedMemorySize, GP_SMEM);
    cudaFuncSetAttribute(tc_gemm_kv_kernel,
        cudaFuncAttributeMaxDynamicSharedMemorySize, SM64);
    cudaFuncSetAttribute(attn_tc_kernel,
        cudaFuncAttributeMaxDynamicSharedMemorySize, ATT2_SMEM_BYTES);

    // tf32 pre-round x, Wq, Wo (RNA)
    {
        int n4x = MROWS*CDIM/4, n4w = CDIM*CDIM/4;
        round4_kernel<<<(n4x + 255)/256, 256>>>((const float4*)x,  (float4*)xr,  n4x);
        round4_kernel<<<(n4w + 255)/256, 256>>>((const float4*)Wq, (float4*)wqr, n4w);
        round4_kernel<<<(n4w + 255)/256, 256>>>((const float4*)Wo, (float4*)wor, n4w);
    }

    // Q = x @ Wq + bq   (pipelined, pre-rounded inputs)
    tc_gemm_pipe_kernel<<<dim3(CDIM/128, MROWS/128), 256, GP_SMEM>>>(
        xr, wqr, bq, qp, MROWS, CDIM, CDIM);
    // K (natural), V (paired) fused
    tc_gemm_kv_kernel<<<dim3(1, MROWS/128, 2), 256, SM64>>>(
        x, Wk, bk, kp, Wv, bv, vp, MROWS, HD, CDIM);

    // RoPE: q in-place, k natural -> paired
    {
        int total = BDIM*TDIM*(NH+1)*(HD/2);
        rope_kernel<<<(total + 255)/256, 256>>>(qp, kp, k2p);
    }

    // causal MQA attention (R8 version, measured best)
    attn_tc_kernel<<<dim3(TDIM/64, NH, BDIM), 128, ATT2_SMEM_BYTES>>>(
        qp, (const float2*)k2p, (const float2*)vp, ap);

    // out = att @ Wo + bo  (pipelined; att pre-rounded by attention)
    tc_gemm_pipe_kernel<<<dim3(CDIM/128, MROWS/128), 256, GP_SMEM>>>(
        ap, wor, bo, out, MROWS, CDIM, CDIM);
}